// round 1
// baseline (speedup 1.0000x reference)
#include <cuda_runtime.h>

// Fused 4-layer MLP: [N,6] -> 128 -> 128 -> 128 -> [N,4], relu between.
// FP32 baseline: weights + double-buffered activations in SMEM,
// 4x4 register microtile per thread, K-unrolled-by-4 float4 LDS.

#define TM        64      // points per CTA
#define NTHREADS  512     // 16 warps

// SMEM layout (floats):
//   sW2  [128][128]  16384
//   sW3  [128][128]  16384
//   sHa  [128][TM]    8192   (feature-major: H[k][p])
//   sHb  [128][TM]    8192
//   sW1  [128][6]      768
//   sW4  [4][128]      512
//   sB1/sB2/sB3       3*128
//   sB4 (+pad)          16
//   sX   [TM][6]       384
static const int SMEM_FLOATS = 16384 + 16384 + 8192 + 8192 + 768 + 512 + 384 + 16 + 384;
static const int SMEM_BYTES  = SMEM_FLOATS * 4;   // 204,864 B

__device__ __forceinline__ float relu(float v) { return fmaxf(v, 0.0f); }

// One 128->128 hidden layer for this thread's 4x4 microtile.
// Hin/Hout are feature-major [128][TM]; W is row-major [j][k] (128x128).
__device__ __forceinline__ void hidden_layer(
    const float* __restrict__ Hin, float* __restrict__ Hout,
    const float* __restrict__ W,   const float* __restrict__ B,
    int p0, int j0)
{
    float acc[4][4];
    #pragma unroll
    for (int ji = 0; ji < 4; ji++) {
        float bv = B[j0 + ji];
        #pragma unroll
        for (int pi = 0; pi < 4; pi++) acc[ji][pi] = bv;
    }

    #pragma unroll 4
    for (int k = 0; k < 128; k += 4) {
        float4 h0 = *(const float4*)&Hin[(k + 0) * TM + p0];
        float4 h1 = *(const float4*)&Hin[(k + 1) * TM + p0];
        float4 h2 = *(const float4*)&Hin[(k + 2) * TM + p0];
        float4 h3 = *(const float4*)&Hin[(k + 3) * TM + p0];
        #pragma unroll
        for (int ji = 0; ji < 4; ji++) {
            float4 w = *(const float4*)&W[(j0 + ji) * 128 + k];
            acc[ji][0] += w.x * h0.x; acc[ji][1] += w.x * h0.y;
            acc[ji][2] += w.x * h0.z; acc[ji][3] += w.x * h0.w;
            acc[ji][0] += w.y * h1.x; acc[ji][1] += w.y * h1.y;
            acc[ji][2] += w.y * h1.z; acc[ji][3] += w.y * h1.w;
            acc[ji][0] += w.z * h2.x; acc[ji][1] += w.z * h2.y;
            acc[ji][2] += w.z * h2.z; acc[ji][3] += w.z * h2.w;
            acc[ji][0] += w.w * h3.x; acc[ji][1] += w.w * h3.y;
            acc[ji][2] += w.w * h3.z; acc[ji][3] += w.w * h3.w;
        }
    }

    #pragma unroll
    for (int ji = 0; ji < 4; ji++) {
        float4 v = make_float4(relu(acc[ji][0]), relu(acc[ji][1]),
                               relu(acc[ji][2]), relu(acc[ji][3]));
        *(float4*)&Hout[(j0 + ji) * TM + p0] = v;
    }
}

__global__ __launch_bounds__(NTHREADS, 1)
void nerf_mlp_kernel(const float* __restrict__ x,
                     const float* __restrict__ W1, const float* __restrict__ b1,
                     const float* __restrict__ W2, const float* __restrict__ b2,
                     const float* __restrict__ W3, const float* __restrict__ b3,
                     const float* __restrict__ W4, const float* __restrict__ b4,
                     float* __restrict__ out)
{
    extern __shared__ float s[];
    float* sW2 = s;                        // 16384
    float* sW3 = sW2 + 16384;              // 16384
    float* sHa = sW3 + 16384;              // 8192
    float* sHb = sHa + 128 * TM;           // 8192
    float* sW1 = sHb + 128 * TM;           // 768
    float* sW4 = sW1 + 768;                // 512
    float* sB1 = sW4 + 512;                // 128
    float* sB2 = sB1 + 128;                // 128
    float* sB3 = sB2 + 128;                // 128
    float* sB4 = sB3 + 128;                // 16 (4 + pad)
    float* sX  = sB4 + 16;                 // 384

    const int tid = threadIdx.x;
    const long long base = (long long)blockIdx.x * TM;

    // ---- cooperative loads into SMEM ----
    for (int i = tid; i < 4096; i += NTHREADS) {
        ((float4*)sW2)[i] = ((const float4*)W2)[i];
        ((float4*)sW3)[i] = ((const float4*)W3)[i];
    }
    for (int i = tid; i < 768; i += NTHREADS) sW1[i] = W1[i];
    for (int i = tid; i < 512; i += NTHREADS) sW4[i] = W4[i];
    if (tid < 128) { sB1[tid] = b1[tid]; sB2[tid] = b2[tid]; sB3[tid] = b3[tid]; }
    if (tid < 4)   { sB4[tid] = b4[tid]; }
    // x tile: TM*6 = 384 floats = 96 float4, 16B-aligned (base*6*4 = 1536B mult.)
    {
        const float4* xg = (const float4*)(x + base * 6);
        for (int i = tid; i < 96; i += NTHREADS) ((float4*)sX)[i] = xg[i];
    }
    __syncthreads();

    const int px = tid & 15;        // 16 point-groups of 4
    const int jx = tid >> 4;        // 32 output-groups of 4
    const int p0 = px * 4;
    const int j0 = jx * 4;

    // ---- layer 1: [6] -> 128 ----
    {
        float acc[4][4];
        #pragma unroll
        for (int ji = 0; ji < 4; ji++) {
            float bv = sB1[j0 + ji];
            #pragma unroll
            for (int pi = 0; pi < 4; pi++) acc[ji][pi] = bv;
        }
        #pragma unroll
        for (int k = 0; k < 6; k++) {
            float xv[4], wv[4];
            #pragma unroll
            for (int pi = 0; pi < 4; pi++) xv[pi] = sX[(p0 + pi) * 6 + k];
            #pragma unroll
            for (int ji = 0; ji < 4; ji++) wv[ji] = sW1[(j0 + ji) * 6 + k];
            #pragma unroll
            for (int ji = 0; ji < 4; ji++)
                #pragma unroll
                for (int pi = 0; pi < 4; pi++)
                    acc[ji][pi] += wv[ji] * xv[pi];
        }
        #pragma unroll
        for (int ji = 0; ji < 4; ji++) {
            float4 v = make_float4(relu(acc[ji][0]), relu(acc[ji][1]),
                                   relu(acc[ji][2]), relu(acc[ji][3]));
            *(float4*)&sHa[(j0 + ji) * TM + p0] = v;
        }
    }
    __syncthreads();

    // ---- layer 2: 128 -> 128 ----
    hidden_layer(sHa, sHb, sW2, sB2, p0, j0);
    __syncthreads();

    // ---- layer 3: 128 -> 128 ----
    hidden_layer(sHb, sHa, sW3, sB3, p0, j0);
    __syncthreads();

    // ---- layer 4: 128 -> 4 (no relu) ----
    if (tid < TM * 4) {
        const int p = tid >> 2;
        const int c = tid & 3;
        float a = sB4[c];
        #pragma unroll 4
        for (int k = 0; k < 128; k += 4) {
            float4 w = *(const float4*)&sW4[c * 128 + k];
            a += sHa[(k + 0) * TM + p] * w.x;
            a += sHa[(k + 1) * TM + p] * w.y;
            a += sHa[(k + 2) * TM + p] * w.z;
            a += sHa[(k + 3) * TM + p] * w.w;
        }
        out[(base + p) * 4 + c] = a;
    }
}

extern "C" void kernel_launch(void* const* d_in, const int* in_sizes, int n_in,
                              void* d_out, int out_size)
{
    const float* x  = (const float*)d_in[0];
    const float* W1 = (const float*)d_in[1];
    const float* b1 = (const float*)d_in[2];
    const float* W2 = (const float*)d_in[3];
    const float* b2 = (const float*)d_in[4];
    const float* W3 = (const float*)d_in[5];
    const float* b3 = (const float*)d_in[6];
    const float* W4 = (const float*)d_in[7];
    const float* b4 = (const float*)d_in[8];
    float* out = (float*)d_out;

    const int n = in_sizes[0] / 6;        // 1048576
    const int grid = n / TM;              // 16384 CTAs

    cudaFuncSetAttribute(nerf_mlp_kernel,
                         cudaFuncAttributeMaxDynamicSharedMemorySize, SMEM_BYTES);
    nerf_mlp_kernel<<<grid, NTHREADS, SMEM_BYTES>>>(
        x, W1, b1, W2, b2, W3, b3, W4, b4, out);
}

// round 3
// speedup vs baseline: 4.0164x; 4.0164x over previous
#include <cuda_runtime.h>
#include <cuda_bf16.h>
#include <cstdint>

// Fused NeRF MLP: [N,6] ->128 ->128 ->128 -> [N,4]
// Hidden layers via mma.sync m16n8k16 bf16 (hi/lo split, 3 passes, f32 accum).
// Activations chain in registers (D-frag == next A-frag). Weights in smem.
// Family-portable PTX only (no tcgen05 -- ptxas target is compute_103).

#define NTHR   256      // 8 warps
#define TILE_M 128      // points per CTA tile
#define WSTRIDE 136     // bf16 row stride for weight tiles (conflict-free)

// ---- smem layout (bytes) ----
#define SM_W2H  0
#define SM_W2L  (SM_W2H + 128*WSTRIDE*2)      // 34816 each
#define SM_W3H  (SM_W2L + 128*WSTRIDE*2)
#define SM_W3L  (SM_W3H + 128*WSTRIDE*2)
#define SM_X    (SM_W3L + 128*WSTRIDE*2)      // 128*6*4 = 3072
#define SM_W1   (SM_X + 3072)                 // 128*6*4 = 3072
#define SM_W4   (SM_W1 + 3072)                // 4*128*4 = 2048
#define SM_B1   (SM_W4 + 2048)                // 512
#define SM_B2   (SM_B1 + 512)
#define SM_B3   (SM_B2 + 512)
#define SM_B4   (SM_B3 + 512)                 // 16
#define SMEM_TOTAL (SM_B4 + 16)

static __device__ __forceinline__ void mma_bf16(float* c, const uint32_t* a,
                                                uint32_t b0, uint32_t b1) {
    asm volatile(
        "mma.sync.aligned.m16n8k16.row.col.f32.bf16.bf16.f32 "
        "{%0,%1,%2,%3},{%4,%5,%6,%7},{%8,%9},{%0,%1,%2,%3};"
        : "+f"(c[0]), "+f"(c[1]), "+f"(c[2]), "+f"(c[3])
        : "r"(a[0]), "r"(a[1]), "r"(a[2]), "r"(a[3]), "r"(b0), "r"(b1));
}

// pack two floats -> bf16x2 reg (lo = v0, hi = v1), round-to-nearest
static __device__ __forceinline__ uint32_t pack_bf16(float v0, float v1) {
    uint32_t r;
    asm("cvt.rn.bf16x2.f32 %0, %1, %2;" : "=r"(r) : "f"(v1), "f"(v0));
    return r;
}
static __device__ __forceinline__ float bf16_rt(float v) {
    return __bfloat162float(__float2bfloat16(v));
}

// d[64] (f32, 16 n-tiles x 4) -> relu -> hi/lo bf16 A-fragments (32+32 regs)
static __device__ __forceinline__ void convert_frags(float* d, uint32_t* ahi,
                                                     uint32_t* alo) {
    #pragma unroll
    for (int i = 0; i < 64; i++) d[i] = fmaxf(d[i], 0.0f);
    #pragma unroll
    for (int K = 0; K < 8; K++) {
        const float* t0 = d + 8 * K;       // tile 2K
        const float* t1 = d + 8 * K + 4;   // tile 2K+1
        #pragma unroll
        for (int i = 0; i < 2; i++) {
            float v0 = t0[2 * i], v1 = t0[2 * i + 1];
            ahi[4 * K + i] = pack_bf16(v0, v1);
            alo[4 * K + i] = pack_bf16(v0 - bf16_rt(v0), v1 - bf16_rt(v1));
            float w0 = t1[2 * i], w1 = t1[2 * i + 1];
            ahi[4 * K + 2 + i] = pack_bf16(w0, w1);
            alo[4 * K + 2 + i] = pack_bf16(w0 - bf16_rt(w0), w1 - bf16_rt(w1));
        }
    }
}

// one 128->128 hidden layer: d = (Ah+Al)(Wh+Wl)^T + bias  (A in regs)
static __device__ __forceinline__ void hidden_layer(
    const uint32_t* ahi, const uint32_t* alo, float* d,
    const __nv_bfloat16* Wh, const __nv_bfloat16* Wl,
    const float* bias, int g, int tig)
{
    #pragma unroll
    for (int t = 0; t < 16; t++) {
        const int jc = 8 * t + 2 * tig;
        float* c = d + 4 * t;
        c[0] = bias[jc]; c[1] = bias[jc + 1]; c[2] = c[0]; c[3] = c[1];
        const __nv_bfloat16* rh = Wh + (8 * t + g) * WSTRIDE + 2 * tig;
        const __nv_bfloat16* rl = Wl + (8 * t + g) * WSTRIDE + 2 * tig;
        #pragma unroll
        for (int K = 0; K < 8; K++) {
            uint32_t bh0 = *(const uint32_t*)(rh + 16 * K);
            uint32_t bh1 = *(const uint32_t*)(rh + 16 * K + 8);
            uint32_t bl0 = *(const uint32_t*)(rl + 16 * K);
            uint32_t bl1 = *(const uint32_t*)(rl + 16 * K + 8);
            mma_bf16(c, ahi + 4 * K, bh0, bh1);
            mma_bf16(c, alo + 4 * K, bh0, bh1);
            mma_bf16(c, ahi + 4 * K, bl0, bl1);
        }
    }
}

__global__ __launch_bounds__(NTHR, 1)
void nerf_mma_kernel(const float* __restrict__ x,
                     const float* __restrict__ W1, const float* __restrict__ b1,
                     const float* __restrict__ W2, const float* __restrict__ b2,
                     const float* __restrict__ W3, const float* __restrict__ b3,
                     const float* __restrict__ W4, const float* __restrict__ b4,
                     float* __restrict__ out, int ntiles)
{
    extern __shared__ char smem[];
    __nv_bfloat16* sW2h = (__nv_bfloat16*)(smem + SM_W2H);
    __nv_bfloat16* sW2l = (__nv_bfloat16*)(smem + SM_W2L);
    __nv_bfloat16* sW3h = (__nv_bfloat16*)(smem + SM_W3H);
    __nv_bfloat16* sW3l = (__nv_bfloat16*)(smem + SM_W3L);
    float* sX  = (float*)(smem + SM_X);
    float* sW1 = (float*)(smem + SM_W1);
    float* sW4 = (float*)(smem + SM_W4);
    float* sB1 = (float*)(smem + SM_B1);
    float* sB2 = (float*)(smem + SM_B2);
    float* sB3 = (float*)(smem + SM_B3);
    float* sB4 = (float*)(smem + SM_B4);

    const int tid  = threadIdx.x;
    const int warp = tid >> 5;
    const int lane = tid & 31;
    const int g    = lane >> 2;   // fragment group (row / B-column)
    const int tig  = lane & 3;    // thread-in-group (k/col pair select)

    // ---- one-time: split weights to bf16 hi/lo, load small params ----
    for (int i = tid; i < 16384; i += NTHR) {
        int r = i >> 7, k = i & 127;
        int o = r * WSTRIDE + k;
        float w2 = W2[i];
        __nv_bfloat16 h2 = __float2bfloat16(w2);
        sW2h[o] = h2;
        sW2l[o] = __float2bfloat16(w2 - __bfloat162float(h2));
        float w3 = W3[i];
        __nv_bfloat16 h3 = __float2bfloat16(w3);
        sW3h[o] = h3;
        sW3l[o] = __float2bfloat16(w3 - __bfloat162float(h3));
    }
    for (int i = tid; i < 768; i += NTHR) sW1[i] = W1[i];
    for (int i = tid; i < 512; i += NTHR) sW4[i] = W4[i];
    if (tid < 128) { sB1[tid] = b1[tid]; sB2[tid] = b2[tid]; sB3[tid] = b3[tid]; }
    if (tid < 4)   sB4[tid] = b4[tid];
    __syncthreads();

    for (int tile = blockIdx.x; tile < ntiles; tile += gridDim.x) {
        const long long base = (long long)tile * TILE_M;

        // ---- stage x tile: 128 x 6 f32 ----
        {
            const float4* xg = (const float4*)(x + base * 6);
            for (int i = tid; i < 192; i += NTHR) ((float4*)sX)[i] = xg[i];
        }
        __syncthreads();

        const int p0 = warp * 16 + g;   // this thread's two points
        const int p1 = p0 + 8;

        float    d[64];
        uint32_t ahi[32], alo[32];

        // ---- layer 1 (SIMT, K=6) directly into fragment layout ----
        {
            float xa[6], xb[6];
            #pragma unroll
            for (int k = 0; k < 6; k++) {
                xa[k] = sX[p0 * 6 + k];
                xb[k] = sX[p1 * 6 + k];
            }
            #pragma unroll
            for (int t = 0; t < 16; t++) {
                int jc = 8 * t + 2 * tig;
                float a0 = sB1[jc], a1 = sB1[jc + 1];
                float b0v = a0, b1v = a1;
                #pragma unroll
                for (int k = 0; k < 6; k++) {
                    float w0 = sW1[jc * 6 + k], w1 = sW1[(jc + 1) * 6 + k];
                    a0  += xa[k] * w0;  a1  += xa[k] * w1;
                    b0v += xb[k] * w0;  b1v += xb[k] * w1;
                }
                d[4 * t + 0] = a0;  d[4 * t + 1] = a1;
                d[4 * t + 2] = b0v; d[4 * t + 3] = b1v;
            }
            convert_frags(d, ahi, alo);
        }

        // ---- layers 2 and 3 (tensor, regs <-> smem weights) ----
        hidden_layer(ahi, alo, d, sW2h, sW2l, sB2, g, tig);
        convert_frags(d, ahi, alo);
        hidden_layer(ahi, alo, d, sW3h, sW3l, sB3, g, tig);

        // ---- layer 4: relu(d) @ W4^T, quad reduction ----
        {
            float oA[4] = {0.f, 0.f, 0.f, 0.f};
            float oB[4] = {0.f, 0.f, 0.f, 0.f};
            #pragma unroll
            for (int t = 0; t < 16; t++) {
                #pragma unroll
                for (int e = 0; e < 2; e++) {
                    int j = 8 * t + 2 * tig + e;
                    float hA = fmaxf(d[4 * t + e],     0.0f);
                    float hB = fmaxf(d[4 * t + 2 + e], 0.0f);
                    #pragma unroll
                    for (int c = 0; c < 4; c++) {
                        float wv = sW4[c * 128 + j];
                        oA[c] += hA * wv;
                        oB[c] += hB * wv;
                    }
                }
            }
            #pragma unroll
            for (int c = 0; c < 4; c++) {
                oA[c] += __shfl_xor_sync(0xFFFFFFFF, oA[c], 1);
                oA[c] += __shfl_xor_sync(0xFFFFFFFF, oA[c], 2);
                oB[c] += __shfl_xor_sync(0xFFFFFFFF, oB[c], 1);
                oB[c] += __shfl_xor_sync(0xFFFFFFFF, oB[c], 2);
            }
            if (tig == 0) {
                float4 ra = make_float4(oA[0] + sB4[0], oA[1] + sB4[1],
                                        oA[2] + sB4[2], oA[3] + sB4[3]);
                float4 rb = make_float4(oB[0] + sB4[0], oB[1] + sB4[1],
                                        oB[2] + sB4[2], oB[3] + sB4[3]);
                *(float4*)(out + (base + p0) * 4) = ra;
                *(float4*)(out + (base + p1) * 4) = rb;
            }
        }
        __syncthreads();   // all warps done with sX before next stage
    }
}

extern "C" void kernel_launch(void* const* d_in, const int* in_sizes, int n_in,
                              void* d_out, int out_size)
{
    const float* x  = (const float*)d_in[0];
    const float* W1 = (const float*)d_in[1];
    const float* b1 = (const float*)d_in[2];
    const float* W2 = (const float*)d_in[3];
    const float* b2 = (const float*)d_in[4];
    const float* W3 = (const float*)d_in[5];
    const float* b3 = (const float*)d_in[6];
    const float* W4 = (const float*)d_in[7];
    const float* b4 = (const float*)d_in[8];
    float* out = (float*)d_out;

    const int n = in_sizes[0] / 6;
    const int ntiles = n / TILE_M;          // 8192
    int grid = 148;
    if (grid > ntiles) grid = ntiles;

    cudaFuncSetAttribute(nerf_mma_kernel,
                         cudaFuncAttributeMaxDynamicSharedMemorySize, SMEM_TOTAL);
    nerf_mma_kernel<<<grid, NTHR, SMEM_TOTAL>>>(
        x, W1, b1, W2, b2, W3, b3, W4, b4, out, ntiles);
}

// round 4
// speedup vs baseline: 4.2196x; 1.0506x over previous
#include <cuda_runtime.h>
#include <cuda_bf16.h>
#include <cstdint>

// Fused NeRF MLP: [N,6] ->128 ->128 ->128 -> [N,4]
// Hidden layers via mma.sync m16n8k16 bf16 (hi/lo split, 3 passes, f32 accum).
// Activations chain in registers (D-frag == next A-frag).
// Weights pre-packed per (ntile,kstep,lane) as 16B {bh0,bh1,bl0,bl1} records:
// one conflict-free LDS.128 feeds 3 MMAs.

#define NTHR   256      // 8 warps
#define TILE_M 128      // points per CTA tile

// packed weight tile: 16 t * 8 K * 32 lanes * 16B = 64 KB per layer
#define PK_BYTES (16*8*32*16)

#define SM_P2   0
#define SM_P3   (SM_P2 + PK_BYTES)
#define SM_X    (SM_P3 + PK_BYTES)           // 128*6*4 = 3072
#define SM_W1   (SM_X + 3072)                // 3072
#define SM_W4   (SM_W1 + 3072)               // 2048
#define SM_B1   (SM_W4 + 2048)               // 512
#define SM_B2   (SM_B1 + 512)
#define SM_B3   (SM_B2 + 512)
#define SM_B4   (SM_B3 + 512)                // 16
#define SMEM_TOTAL (SM_B4 + 16)

static __device__ __forceinline__ void mma_bf16(float* c, const uint32_t* a,
                                                uint32_t b0, uint32_t b1) {
    asm volatile(
        "mma.sync.aligned.m16n8k16.row.col.f32.bf16.bf16.f32 "
        "{%0,%1,%2,%3},{%4,%5,%6,%7},{%8,%9},{%0,%1,%2,%3};"
        : "+f"(c[0]), "+f"(c[1]), "+f"(c[2]), "+f"(c[3])
        : "r"(a[0]), "r"(a[1]), "r"(a[2]), "r"(a[3]), "r"(b0), "r"(b1));
}

static __device__ __forceinline__ uint32_t pack_bf16(float v0, float v1) {
    uint32_t r;
    asm("cvt.rn.bf16x2.f32 %0, %1, %2;" : "=r"(r) : "f"(v1), "f"(v0));
    return r;
}
static __device__ __forceinline__ float bf16_rt(float v) {
    return __bfloat162float(__float2bfloat16(v));
}

// d[64] (f32, 16 n-tiles x 4) -> relu -> hi/lo bf16 A-fragments
static __device__ __forceinline__ void convert_frags(float* d, uint32_t* ahi,
                                                     uint32_t* alo) {
    #pragma unroll
    for (int i = 0; i < 64; i++) d[i] = fmaxf(d[i], 0.0f);
    #pragma unroll
    for (int K = 0; K < 8; K++) {
        const float* t0 = d + 8 * K;       // tile 2K
        const float* t1 = d + 8 * K + 4;   // tile 2K+1
        #pragma unroll
        for (int i = 0; i < 2; i++) {
            float v0 = t0[2 * i], v1 = t0[2 * i + 1];
            ahi[4 * K + i] = pack_bf16(v0, v1);
            alo[4 * K + i] = pack_bf16(v0 - bf16_rt(v0), v1 - bf16_rt(v1));
            float w0 = t1[2 * i], w1 = t1[2 * i + 1];
            ahi[4 * K + 2 + i] = pack_bf16(w0, w1);
            alo[4 * K + 2 + i] = pack_bf16(w0 - bf16_rt(w0), w1 - bf16_rt(w1));
        }
    }
}

// one 128->128 hidden layer from packed fragment records
// pk points at this lane's record stream: pk[(t*8+K)*32]
static __device__ __forceinline__ void hidden_layer(
    const uint32_t* ahi, const uint32_t* alo, float* d,
    const uint4* __restrict__ pk, const float* bias, int tig)
{
    #pragma unroll
    for (int t = 0; t < 16; t++) {
        const int jc = 8 * t + 2 * tig;
        float* c = d + 4 * t;
        c[0] = bias[jc]; c[1] = bias[jc + 1]; c[2] = c[0]; c[3] = c[1];
        #pragma unroll
        for (int K = 0; K < 8; K++) {
            uint4 b = pk[(t * 8 + K) * 32];
            mma_bf16(c, ahi + 4 * K, b.x, b.y);   // Ah * Wh
            mma_bf16(c, alo + 4 * K, b.x, b.y);   // Al * Wh
            mma_bf16(c, ahi + 4 * K, b.z, b.w);   // Ah * Wl
        }
    }
}

__global__ __launch_bounds__(NTHR, 1)
void nerf_mma_kernel(const float* __restrict__ x,
                     const float* __restrict__ W1, const float* __restrict__ b1,
                     const float* __restrict__ W2, const float* __restrict__ b2,
                     const float* __restrict__ W3, const float* __restrict__ b3,
                     const float* __restrict__ W4, const float* __restrict__ b4,
                     float* __restrict__ out, int ntiles)
{
    extern __shared__ char smem[];
    uint4* sP2 = (uint4*)(smem + SM_P2);
    uint4* sP3 = (uint4*)(smem + SM_P3);
    float* sX  = (float*)(smem + SM_X);
    float* sW1 = (float*)(smem + SM_W1);
    float* sW4 = (float*)(smem + SM_W4);
    float* sB1 = (float*)(smem + SM_B1);
    float* sB2 = (float*)(smem + SM_B2);
    float* sB3 = (float*)(smem + SM_B3);
    float* sB4 = (float*)(smem + SM_B4);

    const int tid  = threadIdx.x;
    const int warp = tid >> 5;
    const int lane = tid & 31;
    const int g    = lane >> 2;
    const int tig  = lane & 3;

    // ---- one-time: build packed hi/lo fragment records ----
    // entry e in [0,4096): t=e>>8, K=(e>>5)&7, lane=e&31
    for (int idx = tid; idx < 2 * 4096; idx += NTHR) {
        const int layer = idx >> 12;
        const int e     = idx & 4095;
        const int t   = e >> 8;
        const int K   = (e >> 5) & 7;
        const int ln  = e & 31;
        const int gg  = ln >> 2;
        const int tg  = ln & 3;
        const int j   = 8 * t + gg;
        const int k0  = 16 * K + 2 * tg;
        const float* W = layer ? W3 : W2;
        float w00 = W[j * 128 + k0],     w01 = W[j * 128 + k0 + 1];
        float w10 = W[j * 128 + k0 + 8], w11 = W[j * 128 + k0 + 9];
        uint4 rec;
        rec.x = pack_bf16(bf16_rt(w00), bf16_rt(w01));
        rec.y = pack_bf16(bf16_rt(w10), bf16_rt(w11));
        rec.z = pack_bf16(w00 - bf16_rt(w00), w01 - bf16_rt(w01));
        rec.w = pack_bf16(w10 - bf16_rt(w10), w11 - bf16_rt(w11));
        (layer ? sP3 : sP2)[e] = rec;
    }
    for (int i = tid; i < 768; i += NTHR) sW1[i] = W1[i];
    for (int i = tid; i < 512; i += NTHR) sW4[i] = W4[i];
    if (tid < 128) { sB1[tid] = b1[tid]; sB2[tid] = b2[tid]; sB3[tid] = b3[tid]; }
    if (tid < 4)   sB4[tid] = b4[tid];
    __syncthreads();

    const uint4* pk2 = sP2 + lane;   // lane-strided record streams
    const uint4* pk3 = sP3 + lane;

    for (int tile = blockIdx.x; tile < ntiles; tile += gridDim.x) {
        const long long base = (long long)tile * TILE_M;

        // ---- stage x tile: 128 x 6 f32 ----
        {
            const float4* xg = (const float4*)(x + base * 6);
            for (int i = tid; i < 192; i += NTHR) ((float4*)sX)[i] = xg[i];
        }
        __syncthreads();

        const int p0 = warp * 16 + g;
        const int p1 = p0 + 8;

        float    d[64];
        uint32_t ahi[32], alo[32];

        // ---- layer 1 (SIMT, K=6) directly into fragment layout ----
        {
            float xa[6], xb[6];
            #pragma unroll
            for (int k = 0; k < 6; k++) {
                xa[k] = sX[p0 * 6 + k];
                xb[k] = sX[p1 * 6 + k];
            }
            #pragma unroll
            for (int t = 0; t < 16; t++) {
                int jc = 8 * t + 2 * tig;
                float a0 = sB1[jc], a1 = sB1[jc + 1];
                float b0v = a0, b1v = a1;
                #pragma unroll
                for (int k = 0; k < 6; k++) {
                    float w0 = sW1[jc * 6 + k], w1 = sW1[(jc + 1) * 6 + k];
                    a0  += xa[k] * w0;  a1  += xa[k] * w1;
                    b0v += xb[k] * w0;  b1v += xb[k] * w1;
                }
                d[4 * t + 0] = a0;  d[4 * t + 1] = a1;
                d[4 * t + 2] = b0v; d[4 * t + 3] = b1v;
            }
            convert_frags(d, ahi, alo);
        }

        // ---- layers 2 and 3 (tensor) ----
        hidden_layer(ahi, alo, d, pk2, sB2, tig);
        convert_frags(d, ahi, alo);
        hidden_layer(ahi, alo, d, pk3, sB3, tig);

        // ---- layer 4: relu(d) @ W4^T, quad reduction ----
        {
            float oA[4] = {0.f, 0.f, 0.f, 0.f};
            float oB[4] = {0.f, 0.f, 0.f, 0.f};
            #pragma unroll
            for (int t = 0; t < 16; t++) {
                #pragma unroll
                for (int e = 0; e < 2; e++) {
                    int j = 8 * t + 2 * tig + e;
                    float hA = fmaxf(d[4 * t + e],     0.0f);
                    float hB = fmaxf(d[4 * t + 2 + e], 0.0f);
                    #pragma unroll
                    for (int c = 0; c < 4; c++) {
                        float wv = sW4[c * 128 + j];
                        oA[c] += hA * wv;
                        oB[c] += hB * wv;
                    }
                }
            }
            #pragma unroll
            for (int c = 0; c < 4; c++) {
                oA[c] += __shfl_xor_sync(0xFFFFFFFF, oA[c], 1);
                oA[c] += __shfl_xor_sync(0xFFFFFFFF, oA[c], 2);
                oB[c] += __shfl_xor_sync(0xFFFFFFFF, oB[c], 1);
                oB[c] += __shfl_xor_sync(0xFFFFFFFF, oB[c], 2);
            }
            if (tig == 0) {
                float4 ra = make_float4(oA[0] + sB4[0], oA[1] + sB4[1],
                                        oA[2] + sB4[2], oA[3] + sB4[3]);
                float4 rb = make_float4(oB[0] + sB4[0], oB[1] + sB4[1],
                                        oB[2] + sB4[2], oB[3] + sB4[3]);
                *(float4*)(out + (base + p0) * 4) = ra;
                *(float4*)(out + (base + p1) * 4) = rb;
            }
        }
        __syncthreads();   // all warps done with sX before restage
    }
}

extern "C" void kernel_launch(void* const* d_in, const int* in_sizes, int n_in,
                              void* d_out, int out_size)
{
    const float* x  = (const float*)d_in[0];
    const float* W1 = (const float*)d_in[1];
    const float* b1 = (const float*)d_in[2];
    const float* W2 = (const float*)d_in[3];
    const float* b2 = (const float*)d_in[4];
    const float* W3 = (const float*)d_in[5];
    const float* b3 = (const float*)d_in[6];
    const float* W4 = (const float*)d_in[7];
    const float* b4 = (const float*)d_in[8];
    float* out = (float*)d_out;

    const int n = in_sizes[0] / 6;
    const int ntiles = n / TILE_M;          // 8192
    int grid = 148;
    if (grid > ntiles) grid = ntiles;

    cudaFuncSetAttribute(nerf_mma_kernel,
                         cudaFuncAttributeMaxDynamicSharedMemorySize, SMEM_TOTAL);
    nerf_mma_kernel<<<grid, NTHR, SMEM_TOTAL>>>(
        x, W1, b1, W2, b2, W3, b3, W4, b4, out, ntiles);
}

// round 5
// speedup vs baseline: 5.6883x; 1.3481x over previous
#include <cuda_runtime.h>
#include <cuda_fp16.h>
#include <cstdint>

// Fused NeRF MLP: [N,6] ->128 ->128 ->128 -> [N,4]
// Hidden layers via mma.sync m16n8k16 fp16 (W split hi/lo exactly, A rounded
// once -> 2 passes, f32 accum). Activations chain in registers.
// Weights pre-packed per (ntile,kstep,lane) as 16B {wh0,wh1,wl0,wl1} records:
// one conflict-free LDS.128 feeds 2 MMAs. No barriers in the tile loop.

#define NTHR   256      // 8 warps
#define TILE_M 128      // points per CTA tile

// packed weight tile: 16 t * 8 K * 32 lanes * 16B = 64 KB per layer
#define PK_BYTES (16*8*32*16)

#define SM_P2   0
#define SM_P3   (SM_P2 + PK_BYTES)
#define SM_W1   (SM_P3 + PK_BYTES)           // 128*6*4 = 3072
#define SM_W4   (SM_W1 + 3072)               // 2048
#define SM_B1   (SM_W4 + 2048)               // 512
#define SM_B2   (SM_B1 + 512)
#define SM_B3   (SM_B2 + 512)
#define SM_B4   (SM_B3 + 512)                // 16
#define SMEM_TOTAL (SM_B4 + 16)

static __device__ __forceinline__ void mma_f16(float* c, const uint32_t* a,
                                               uint32_t b0, uint32_t b1) {
    asm volatile(
        "mma.sync.aligned.m16n8k16.row.col.f32.f16.f16.f32 "
        "{%0,%1,%2,%3},{%4,%5,%6,%7},{%8,%9},{%0,%1,%2,%3};"
        : "+f"(c[0]), "+f"(c[1]), "+f"(c[2]), "+f"(c[3])
        : "r"(a[0]), "r"(a[1]), "r"(a[2]), "r"(a[3]), "r"(b0), "r"(b1));
}

// pack two floats -> f16x2 reg (lo = v0, hi = v1), round-to-nearest
static __device__ __forceinline__ uint32_t pack_f16(float v0, float v1) {
    uint32_t r;
    asm("cvt.rn.f16x2.f32 %0, %1, %2;" : "=r"(r) : "f"(v1), "f"(v0));
    return r;
}
static __device__ __forceinline__ float f16_rt(float v) {
    return __half2float(__float2half_rn(v));
}

// d[64] (f32, 16 n-tiles x 4) -> relu -> fp16 A-fragments (32 regs)
static __device__ __forceinline__ void convert_frags(float* d, uint32_t* ahi) {
    #pragma unroll
    for (int i = 0; i < 64; i++) d[i] = fmaxf(d[i], 0.0f);
    #pragma unroll
    for (int K = 0; K < 8; K++) {
        const float* t0 = d + 8 * K;       // tile 2K
        const float* t1 = d + 8 * K + 4;   // tile 2K+1
        ahi[4 * K + 0] = pack_f16(t0[0], t0[1]);
        ahi[4 * K + 1] = pack_f16(t0[2], t0[3]);
        ahi[4 * K + 2] = pack_f16(t1[0], t1[1]);
        ahi[4 * K + 3] = pack_f16(t1[2], t1[3]);
    }
}

// one 128->128 hidden layer from packed fragment records
// pk points at this lane's record stream: pk[(t*8+K)*32]
static __device__ __forceinline__ void hidden_layer(
    const uint32_t* a, float* d,
    const uint4* __restrict__ pk, const float* bias, int tig)
{
    #pragma unroll
    for (int t = 0; t < 16; t++) {
        const int jc = 8 * t + 2 * tig;
        float* c = d + 4 * t;
        c[0] = bias[jc]; c[1] = bias[jc + 1]; c[2] = c[0]; c[3] = c[1];
        #pragma unroll
        for (int K = 0; K < 8; K++) {
            uint4 b = pk[(t * 8 + K) * 32];
            mma_f16(c, a + 4 * K, b.x, b.y);   // A * Wh
            mma_f16(c, a + 4 * K, b.z, b.w);   // A * Wl
        }
    }
}

__global__ __launch_bounds__(NTHR, 1)
void nerf_mma_kernel(const float* __restrict__ x,
                     const float* __restrict__ W1, const float* __restrict__ b1,
                     const float* __restrict__ W2, const float* __restrict__ b2,
                     const float* __restrict__ W3, const float* __restrict__ b3,
                     const float* __restrict__ W4, const float* __restrict__ b4,
                     float* __restrict__ out, int ntiles)
{
    extern __shared__ char smem[];
    uint4* sP2 = (uint4*)(smem + SM_P2);
    uint4* sP3 = (uint4*)(smem + SM_P3);
    float* sW1 = (float*)(smem + SM_W1);
    float* sW4 = (float*)(smem + SM_W4);
    float* sB1 = (float*)(smem + SM_B1);
    float* sB2 = (float*)(smem + SM_B2);
    float* sB3 = (float*)(smem + SM_B3);
    float* sB4 = (float*)(smem + SM_B4);

    const int tid  = threadIdx.x;
    const int warp = tid >> 5;
    const int lane = tid & 31;
    const int g    = lane >> 2;
    const int tig  = lane & 3;

    // ---- one-time: build packed fp16 hi/lo weight fragment records ----
    // entry e in [0,4096): t=e>>8, K=(e>>5)&7, lane=e&31
    for (int idx = tid; idx < 2 * 4096; idx += NTHR) {
        const int layer = idx >> 12;
        const int e     = idx & 4095;
        const int t   = e >> 8;
        const int K   = (e >> 5) & 7;
        const int ln  = e & 31;
        const int gg  = ln >> 2;
        const int tg  = ln & 3;
        const int j   = 8 * t + gg;
        const int k0  = 16 * K + 2 * tg;
        const float* W = layer ? W3 : W2;
        float w00 = W[j * 128 + k0],     w01 = W[j * 128 + k0 + 1];
        float w10 = W[j * 128 + k0 + 8], w11 = W[j * 128 + k0 + 9];
        uint4 rec;
        rec.x = pack_f16(f16_rt(w00), f16_rt(w01));
        rec.y = pack_f16(f16_rt(w10), f16_rt(w11));
        rec.z = pack_f16(w00 - f16_rt(w00), w01 - f16_rt(w01));
        rec.w = pack_f16(w10 - f16_rt(w10), w11 - f16_rt(w11));
        (layer ? sP3 : sP2)[e] = rec;
    }
    for (int i = tid; i < 768; i += NTHR) sW1[i] = W1[i];
    for (int i = tid; i < 512; i += NTHR) sW4[i] = W4[i];
    if (tid < 128) { sB1[tid] = b1[tid]; sB2[tid] = b2[tid]; sB3[tid] = b3[tid]; }
    if (tid < 4)   sB4[tid] = b4[tid];
    __syncthreads();

    const uint4* pk2 = sP2 + lane;   // lane-strided record streams
    const uint4* pk3 = sP3 + lane;

    for (int tile = blockIdx.x; tile < ntiles; tile += gridDim.x) {
        const long long base = (long long)tile * TILE_M;

        const int p0 = warp * 16 + g;
        const int p1 = p0 + 8;

        float    d[64];
        uint32_t a[32];

        // ---- layer 1 (SIMT, K=6) directly into fragment layout ----
        {
            float xa[6], xb[6];
            const float* xr0 = x + (base + p0) * 6;
            const float* xr1 = x + (base + p1) * 6;
            #pragma unroll
            for (int k = 0; k < 6; k++) { xa[k] = xr0[k]; xb[k] = xr1[k]; }
            #pragma unroll
            for (int t = 0; t < 16; t++) {
                int jc = 8 * t + 2 * tig;
                float a0 = sB1[jc], a1 = sB1[jc + 1];
                float b0v = a0, b1v = a1;
                #pragma unroll
                for (int k = 0; k < 6; k++) {
                    float w0 = sW1[jc * 6 + k], w1 = sW1[(jc + 1) * 6 + k];
                    a0  += xa[k] * w0;  a1  += xa[k] * w1;
                    b0v += xb[k] * w0;  b1v += xb[k] * w1;
                }
                d[4 * t + 0] = a0;  d[4 * t + 1] = a1;
                d[4 * t + 2] = b0v; d[4 * t + 3] = b1v;
            }
            convert_frags(d, a);
        }

        // ---- layers 2 and 3 (tensor) ----
        hidden_layer(a, d, pk2, sB2, tig);
        convert_frags(d, a);
        hidden_layer(a, d, pk3, sB3, tig);

        // ---- layer 4: relu(d) @ W4^T, quad reduction ----
        {
            float oA[4] = {0.f, 0.f, 0.f, 0.f};
            float oB[4] = {0.f, 0.f, 0.f, 0.f};
            #pragma unroll
            for (int t = 0; t < 16; t++) {
                #pragma unroll
                for (int e = 0; e < 2; e++) {
                    int j = 8 * t + 2 * tig + e;
                    float hA = fmaxf(d[4 * t + e],     0.0f);
                    float hB = fmaxf(d[4 * t + 2 + e], 0.0f);
                    #pragma unroll
                    for (int c = 0; c < 4; c++) {
                        float wv = sW4[c * 128 + j];
                        oA[c] += hA * wv;
                        oB[c] += hB * wv;
                    }
                }
            }
            #pragma unroll
            for (int c = 0; c < 4; c++) {
                oA[c] += __shfl_xor_sync(0xFFFFFFFF, oA[c], 1);
                oA[c] += __shfl_xor_sync(0xFFFFFFFF, oA[c], 2);
                oB[c] += __shfl_xor_sync(0xFFFFFFFF, oB[c], 1);
                oB[c] += __shfl_xor_sync(0xFFFFFFFF, oB[c], 2);
            }
            if (tig == 0) {
                float4 ra = make_float4(oA[0] + sB4[0], oA[1] + sB4[1],
                                        oA[2] + sB4[2], oA[3] + sB4[3]);
                float4 rb = make_float4(oB[0] + sB4[0], oB[1] + sB4[1],
                                        oB[2] + sB4[2], oB[3] + sB4[3]);
                *(float4*)(out + (base + p0) * 4) = ra;
                *(float4*)(out + (base + p1) * 4) = rb;
            }
        }
        // no barriers needed: no per-tile shared state
    }
}

extern "C" void kernel_launch(void* const* d_in, const int* in_sizes, int n_in,
                              void* d_out, int out_size)
{
    const float* x  = (const float*)d_in[0];
    const float* W1 = (const float*)d_in[1];
    const float* b1 = (const float*)d_in[2];
    const float* W2 = (const float*)d_in[3];
    const float* b2 = (const float*)d_in[4];
    const float* W3 = (const float*)d_in[5];
    const float* b3 = (const float*)d_in[6];
    const float* W4 = (const float*)d_in[7];
    const float* b4 = (const float*)d_in[8];
    float* out = (float*)d_out;

    const int n = in_sizes[0] / 6;
    const int ntiles = n / TILE_M;          // 8192
    int grid = 148;
    if (grid > ntiles) grid = ntiles;

    cudaFuncSetAttribute(nerf_mma_kernel,
                         cudaFuncAttributeMaxDynamicSharedMemorySize, SMEM_TOTAL);
    nerf_mma_kernel<<<grid, NTHR, SMEM_TOTAL>>>(
        x, W1, b1, W2, b2, W3, b3, W4, b4, out, ntiles);
}

// round 6
// speedup vs baseline: 8.5919x; 1.5104x over previous
#include <cuda_runtime.h>
#include <cuda_fp16.h>
#include <cstdint>

// Fused NeRF MLP: [N,6] ->128 ->128 ->128 -> [N,4]
// Hidden layers via mma.sync m16n8k16 fp16 single-pass (W and A rounded to
// fp16, f32 accum). Activations chain in registers (D-frag == next A-frag).
// Weights pre-packed per (ntile, kpair, lane) as 16B {b0(K),b1(K),b0(K+1),
// b1(K+1)}: one conflict-free LDS.128 feeds 2 MMAs. No barriers in tile loop.

#define NTHR   256      // 8 warps
#define TILE_M 128      // points per CTA tile

// packed weight tile: 16 t * 4 Kp * 32 lanes * 16B = 32 KB per layer
#define PK_BYTES (16*4*32*16)

#define SM_P2   0
#define SM_P3   (SM_P2 + PK_BYTES)
#define SM_W1   (SM_P3 + PK_BYTES)           // 128*6*4 = 3072
#define SM_W4   (SM_W1 + 3072)               // 2048
#define SM_B1   (SM_W4 + 2048)               // 512
#define SM_B2   (SM_B1 + 512)
#define SM_B3   (SM_B2 + 512)
#define SM_B4   (SM_B3 + 512)                // 16
#define SMEM_TOTAL (SM_B4 + 16)

static __device__ __forceinline__ void mma_f16(float* c, const uint32_t* a,
                                               uint32_t b0, uint32_t b1) {
    asm volatile(
        "mma.sync.aligned.m16n8k16.row.col.f32.f16.f16.f32 "
        "{%0,%1,%2,%3},{%4,%5,%6,%7},{%8,%9},{%0,%1,%2,%3};"
        : "+f"(c[0]), "+f"(c[1]), "+f"(c[2]), "+f"(c[3])
        : "r"(a[0]), "r"(a[1]), "r"(a[2]), "r"(a[3]), "r"(b0), "r"(b1));
}

// pack two floats -> f16x2 reg (lo = v0, hi = v1), round-to-nearest
static __device__ __forceinline__ uint32_t pack_f16(float v0, float v1) {
    uint32_t r;
    asm("cvt.rn.f16x2.f32 %0, %1, %2;" : "=r"(r) : "f"(v1), "f"(v0));
    return r;
}

// d[64] (f32, 16 n-tiles x 4) -> relu -> fp16 A-fragments (32 regs)
static __device__ __forceinline__ void convert_frags(float* d, uint32_t* a) {
    #pragma unroll
    for (int i = 0; i < 64; i++) d[i] = fmaxf(d[i], 0.0f);
    #pragma unroll
    for (int K = 0; K < 8; K++) {
        const float* t0 = d + 8 * K;       // tile 2K
        const float* t1 = d + 8 * K + 4;   // tile 2K+1
        a[4 * K + 0] = pack_f16(t0[0], t0[1]);
        a[4 * K + 1] = pack_f16(t0[2], t0[3]);
        a[4 * K + 2] = pack_f16(t1[0], t1[1]);
        a[4 * K + 3] = pack_f16(t1[2], t1[3]);
    }
}

// one 128->128 hidden layer from packed fragment records
// pk points at this lane's record stream: pk[(t*4+Kp)*32]
// record = {b0(K=2Kp), b1(K=2Kp), b0(K=2Kp+1), b1(K=2Kp+1)}
static __device__ __forceinline__ void hidden_layer(
    const uint32_t* a, float* d,
    const uint4* __restrict__ pk, const float* bias, int tig)
{
    #pragma unroll
    for (int t = 0; t < 16; t++) {
        const int jc = 8 * t + 2 * tig;
        float* c = d + 4 * t;
        c[0] = bias[jc]; c[1] = bias[jc + 1]; c[2] = c[0]; c[3] = c[1];
        #pragma unroll
        for (int Kp = 0; Kp < 4; Kp++) {
            uint4 b = pk[(t * 4 + Kp) * 32];
            mma_f16(c, a + 8 * Kp,     b.x, b.y);   // K = 2Kp
            mma_f16(c, a + 8 * Kp + 4, b.z, b.w);   // K = 2Kp+1
        }
    }
}

__global__ __launch_bounds__(NTHR, 1)
void nerf_mma_kernel(const float* __restrict__ x,
                     const float* __restrict__ W1, const float* __restrict__ b1,
                     const float* __restrict__ W2, const float* __restrict__ b2,
                     const float* __restrict__ W3, const float* __restrict__ b3,
                     const float* __restrict__ W4, const float* __restrict__ b4,
                     float* __restrict__ out, int ntiles)
{
    extern __shared__ char smem[];
    uint4* sP2 = (uint4*)(smem + SM_P2);
    uint4* sP3 = (uint4*)(smem + SM_P3);
    float* sW1 = (float*)(smem + SM_W1);
    float* sW4 = (float*)(smem + SM_W4);
    float* sB1 = (float*)(smem + SM_B1);
    float* sB2 = (float*)(smem + SM_B2);
    float* sB3 = (float*)(smem + SM_B3);
    float* sB4 = (float*)(smem + SM_B4);

    const int tid  = threadIdx.x;
    const int warp = tid >> 5;
    const int lane = tid & 31;
    const int g    = lane >> 2;
    const int tig  = lane & 3;

    // ---- one-time: build packed fp16 weight fragment records ----
    // entry e in [0,2048): t=e>>7, Kp=(e>>5)&3, lane=e&31
    for (int idx = tid; idx < 2 * 2048; idx += NTHR) {
        const int layer = idx >> 11;
        const int e     = idx & 2047;
        const int t   = e >> 7;
        const int Kp  = (e >> 5) & 3;
        const int ln  = e & 31;
        const int gg  = ln >> 2;
        const int tg  = ln & 3;
        const int j   = 8 * t + gg;
        const int k0  = 32 * Kp + 2 * tg;       // K = 2Kp
        const float* W = layer ? W3 : W2;
        uint4 rec;
        rec.x = pack_f16(W[j * 128 + k0],      W[j * 128 + k0 + 1]);
        rec.y = pack_f16(W[j * 128 + k0 + 8],  W[j * 128 + k0 + 9]);
        rec.z = pack_f16(W[j * 128 + k0 + 16], W[j * 128 + k0 + 17]);
        rec.w = pack_f16(W[j * 128 + k0 + 24], W[j * 128 + k0 + 25]);
        (layer ? sP3 : sP2)[e] = rec;
    }
    for (int i = tid; i < 768; i += NTHR) sW1[i] = W1[i];
    for (int i = tid; i < 512; i += NTHR) sW4[i] = W4[i];
    if (tid < 128) { sB1[tid] = b1[tid]; sB2[tid] = b2[tid]; sB3[tid] = b3[tid]; }
    if (tid < 4)   sB4[tid] = b4[tid];
    __syncthreads();

    const uint4* pk2 = sP2 + lane;   // lane-strided record streams
    const uint4* pk3 = sP3 + lane;

    for (int tile = blockIdx.x; tile < ntiles; tile += gridDim.x) {
        const long long base = (long long)tile * TILE_M;

        const int p0 = warp * 16 + g;
        const int p1 = p0 + 8;

        float    d[64];
        uint32_t a[32];

        // ---- layer 1 (SIMT, K=6) directly into fragment layout ----
        {
            float xa[6], xb[6];
            const float* xr0 = x + (base + p0) * 6;
            const float* xr1 = x + (base + p1) * 6;
            #pragma unroll
            for (int k = 0; k < 6; k++) { xa[k] = xr0[k]; xb[k] = xr1[k]; }
            #pragma unroll
            for (int t = 0; t < 16; t++) {
                int jc = 8 * t + 2 * tig;
                float a0 = sB1[jc], a1 = sB1[jc + 1];
                float b0v = a0, b1v = a1;
                #pragma unroll
                for (int k = 0; k < 6; k++) {
                    float w0 = sW1[jc * 6 + k], w1 = sW1[(jc + 1) * 6 + k];
                    a0  += xa[k] * w0;  a1  += xa[k] * w1;
                    b0v += xb[k] * w0;  b1v += xb[k] * w1;
                }
                d[4 * t + 0] = a0;  d[4 * t + 1] = a1;
                d[4 * t + 2] = b0v; d[4 * t + 3] = b1v;
            }
            convert_frags(d, a);
        }

        // ---- layers 2 and 3 (tensor, single fp16 pass each) ----
        hidden_layer(a, d, pk2, sB2, tig);
        convert_frags(d, a);
        hidden_layer(a, d, pk3, sB3, tig);

        // ---- layer 4: relu(d) @ W4^T, quad reduction ----
        {
            float oA[4] = {0.f, 0.f, 0.f, 0.f};
            float oB[4] = {0.f, 0.f, 0.f, 0.f};
            #pragma unroll
            for (int t = 0; t < 16; t++) {
                #pragma unroll
                for (int e = 0; e < 2; e++) {
                    int j = 8 * t + 2 * tig + e;
                    float hA = fmaxf(d[4 * t + e],     0.0f);
                    float hB = fmaxf(d[4 * t + 2 + e], 0.0f);
                    #pragma unroll
                    for (int c = 0; c < 4; c++) {
                        float wv = sW4[c * 128 + j];
                        oA[c] += hA * wv;
                        oB[c] += hB * wv;
                    }
                }
            }
            #pragma unroll
            for (int c = 0; c < 4; c++) {
                oA[c] += __shfl_xor_sync(0xFFFFFFFF, oA[c], 1);
                oA[c] += __shfl_xor_sync(0xFFFFFFFF, oA[c], 2);
                oB[c] += __shfl_xor_sync(0xFFFFFFFF, oB[c], 1);
                oB[c] += __shfl_xor_sync(0xFFFFFFFF, oB[c], 2);
            }
            if (tig == 0) {
                float4 ra = make_float4(oA[0] + sB4[0], oA[1] + sB4[1],
                                        oA[2] + sB4[2], oA[3] + sB4[3]);
                float4 rb = make_float4(oB[0] + sB4[0], oB[1] + sB4[1],
                                        oB[2] + sB4[2], oB[3] + sB4[3]);
                *(float4*)(out + (base + p0) * 4) = ra;
                *(float4*)(out + (base + p1) * 4) = rb;
            }
        }
        // no barriers needed: no per-tile shared state
    }
}

extern "C" void kernel_launch(void* const* d_in, const int* in_sizes, int n_in,
                              void* d_out, int out_size)
{
    const float* x  = (const float*)d_in[0];
    const float* W1 = (const float*)d_in[1];
    const float* b1 = (const float*)d_in[2];
    const float* W2 = (const float*)d_in[3];
    const float* b2 = (const float*)d_in[4];
    const float* W3 = (const float*)d_in[5];
    const float* b3 = (const float*)d_in[6];
    const float* W4 = (const float*)d_in[7];
    const float* b4 = (const float*)d_in[8];
    float* out = (float*)d_out;

    const int n = in_sizes[0] / 6;
    const int ntiles = n / TILE_M;          // 8192
    int grid = 148;
    if (grid > ntiles) grid = ntiles;

    cudaFuncSetAttribute(nerf_mma_kernel,
                         cudaFuncAttributeMaxDynamicSharedMemorySize, SMEM_TOTAL);
    nerf_mma_kernel<<<grid, NTHR, SMEM_TOTAL>>>(
        x, W1, b1, W2, b2, W3, b3, W4, b4, out, ntiles);
}

// round 7
// speedup vs baseline: 9.7731x; 1.1375x over previous
#include <cuda_runtime.h>
#include <cuda_fp16.h>
#include <cstdint>

// Fused NeRF MLP: [N,6] ->128 ->128 ->128 -> [N,4]
// Hidden layers: mma.sync m16n8k16 fp16 single-pass, f32 accum.
// Each warp processes 32 points as two m16 rowsets (A/B); every weight
// LDS.128 record feeds 4 MMAs (2 k-halves x 2 rowsets) -> half the smem
// crossbar bytes per point. Activations chain entirely in registers.

#define NTHR   256      // 8 warps
#define TILE_M 256      // points per CTA tile (32 per warp)

// packed weight tile: 16 t * 4 Kp * 32 lanes * 16B = 32 KB per layer
#define PK_BYTES (16*4*32*16)

#define SM_P2   0
#define SM_P3   (SM_P2 + PK_BYTES)
#define SM_W1   (SM_P3 + PK_BYTES)           // 128*6*4 = 3072
#define SM_W4   (SM_W1 + 3072)               // 2048
#define SM_B1   (SM_W4 + 2048)               // 512
#define SM_B2   (SM_B1 + 512)
#define SM_B3   (SM_B2 + 512)
#define SM_B4   (SM_B3 + 512)                // 16
#define SMEM_TOTAL (SM_B4 + 16)

static __device__ __forceinline__ void mma_f16(float* c, const uint32_t* a,
                                               uint32_t b0, uint32_t b1) {
    asm volatile(
        "mma.sync.aligned.m16n8k16.row.col.f32.f16.f16.f32 "
        "{%0,%1,%2,%3},{%4,%5,%6,%7},{%8,%9},{%0,%1,%2,%3};"
        : "+f"(c[0]), "+f"(c[1]), "+f"(c[2]), "+f"(c[3])
        : "r"(a[0]), "r"(a[1]), "r"(a[2]), "r"(a[3]), "r"(b0), "r"(b1));
}

static __device__ __forceinline__ uint32_t pack_f16(float v0, float v1) {
    uint32_t r;
    asm("cvt.rn.f16x2.f32 %0, %1, %2;" : "=r"(r) : "f"(v1), "f"(v0));
    return r;
}

// relu + pack one finished n-tile (c[4]) into a-frag slots for k-tile K=t>>1
static __device__ __forceinline__ void pack_tile(uint32_t* a, int t,
                                                 const float* c) {
    const int K = t >> 1;
    const int o = (t & 1) ? (4 * K + 2) : (4 * K);
    a[o]     = pack_f16(fmaxf(c[0], 0.f), fmaxf(c[1], 0.f));
    a[o + 1] = pack_f16(fmaxf(c[2], 0.f), fmaxf(c[3], 0.f));
}

__global__ __launch_bounds__(NTHR, 1)
void nerf_mma_kernel(const float* __restrict__ x,
                     const float* __restrict__ W1, const float* __restrict__ b1,
                     const float* __restrict__ W2, const float* __restrict__ b2,
                     const float* __restrict__ W3, const float* __restrict__ b3,
                     const float* __restrict__ W4, const float* __restrict__ b4,
                     float* __restrict__ out, int ntiles)
{
    extern __shared__ char smem[];
    uint4* sP2 = (uint4*)(smem + SM_P2);
    uint4* sP3 = (uint4*)(smem + SM_P3);
    float* sW1 = (float*)(smem + SM_W1);
    float* sW4 = (float*)(smem + SM_W4);
    float* sB1 = (float*)(smem + SM_B1);
    float* sB2 = (float*)(smem + SM_B2);
    float* sB3 = (float*)(smem + SM_B3);
    float* sB4 = (float*)(smem + SM_B4);

    const int tid  = threadIdx.x;
    const int warp = tid >> 5;
    const int lane = tid & 31;
    const int g    = lane >> 2;
    const int tig  = lane & 3;

    // ---- one-time: build packed fp16 weight fragment records ----
    // entry e in [0,2048): t=e>>7, Kp=(e>>5)&3, lane=e&31
    for (int idx = tid; idx < 2 * 2048; idx += NTHR) {
        const int layer = idx >> 11;
        const int e     = idx & 2047;
        const int t   = e >> 7;
        const int Kp  = (e >> 5) & 3;
        const int ln  = e & 31;
        const int gg  = ln >> 2;
        const int tg  = ln & 3;
        const int j   = 8 * t + gg;
        const int k0  = 32 * Kp + 2 * tg;
        const float* W = layer ? W3 : W2;
        uint4 rec;
        rec.x = pack_f16(W[j * 128 + k0],      W[j * 128 + k0 + 1]);
        rec.y = pack_f16(W[j * 128 + k0 + 8],  W[j * 128 + k0 + 9]);
        rec.z = pack_f16(W[j * 128 + k0 + 16], W[j * 128 + k0 + 17]);
        rec.w = pack_f16(W[j * 128 + k0 + 24], W[j * 128 + k0 + 25]);
        (layer ? sP3 : sP2)[e] = rec;
    }
    for (int i = tid; i < 768; i += NTHR) sW1[i] = W1[i];
    for (int i = tid; i < 512; i += NTHR) sW4[i] = W4[i];
    if (tid < 128) { sB1[tid] = b1[tid]; sB2[tid] = b2[tid]; sB3[tid] = b3[tid]; }
    if (tid < 4)   sB4[tid] = b4[tid];
    __syncthreads();

    const uint4* pk2 = sP2 + lane;
    const uint4* pk3 = sP3 + lane;

    for (int tile = blockIdx.x; tile < ntiles; tile += gridDim.x) {
        const long long base = (long long)tile * TILE_M;
        const int pw = warp * 32;           // warp's 32-point window
        // this thread's 4 points: rows g, g+8 (rowset A), g+16, g+24 (B)

        uint32_t aA1[32], aB1[32];          // layer-1 output frags
        uint32_t aA2[32], aB2[32];          // layer-2 output frags

        // ---- layer 1 (SIMT, K=6) into fragment layout ----
        {
            float xr[4][6];
            #pragma unroll
            for (int r = 0; r < 4; r++) {
                const float* xp = x + (base + pw + g + 8 * r) * 6;
                #pragma unroll
                for (int k = 0; k < 6; k++) xr[r][k] = xp[k];
            }
            #pragma unroll
            for (int t = 0; t < 16; t++) {
                const int jc = 8 * t + 2 * tig;
                float w[6][2];
                #pragma unroll
                for (int k = 0; k < 6; k++) {
                    w[k][0] = sW1[jc * 6 + k];
                    w[k][1] = sW1[(jc + 1) * 6 + k];
                }
                float cA[4], cB[4];
                cA[0] = cA[2] = cB[0] = cB[2] = sB1[jc];
                cA[1] = cA[3] = cB[1] = cB[3] = sB1[jc + 1];
                #pragma unroll
                for (int k = 0; k < 6; k++) {
                    cA[0] += xr[0][k] * w[k][0];  cA[1] += xr[0][k] * w[k][1];
                    cA[2] += xr[1][k] * w[k][0];  cA[3] += xr[1][k] * w[k][1];
                    cB[0] += xr[2][k] * w[k][0];  cB[1] += xr[2][k] * w[k][1];
                    cB[2] += xr[3][k] * w[k][0];  cB[3] += xr[3][k] * w[k][1];
                }
                pack_tile(aA1, t, cA);
                pack_tile(aB1, t, cB);
            }
        }

        // ---- layer 2 (tensor): a1 -> a2 ----
        #pragma unroll
        for (int t = 0; t < 16; t++) {
            const int jc = 8 * t + 2 * tig;
            float cA[4], cB[4];
            cA[0] = cA[2] = cB[0] = cB[2] = sB2[jc];
            cA[1] = cA[3] = cB[1] = cB[3] = sB2[jc + 1];
            #pragma unroll
            for (int Kp = 0; Kp < 4; Kp++) {
                uint4 b = pk2[(t * 4 + Kp) * 32];
                mma_f16(cA, aA1 + 8 * Kp,     b.x, b.y);
                mma_f16(cA, aA1 + 8 * Kp + 4, b.z, b.w);
                mma_f16(cB, aB1 + 8 * Kp,     b.x, b.y);
                mma_f16(cB, aB1 + 8 * Kp + 4, b.z, b.w);
            }
            pack_tile(aA2, t, cA);
            pack_tile(aB2, t, cB);
        }

        // ---- layer 3 (tensor) + layer 4 fused per n-tile ----
        float o[4][4];
        #pragma unroll
        for (int r = 0; r < 4; r++)
            #pragma unroll
            for (int c = 0; c < 4; c++) o[r][c] = 0.f;

        #pragma unroll
        for (int t = 0; t < 16; t++) {
            const int jc = 8 * t + 2 * tig;
            float cA[4], cB[4];
            cA[0] = cA[2] = cB[0] = cB[2] = sB3[jc];
            cA[1] = cA[3] = cB[1] = cB[3] = sB3[jc + 1];
            #pragma unroll
            for (int Kp = 0; Kp < 4; Kp++) {
                uint4 b = pk3[(t * 4 + Kp) * 32];
                mma_f16(cA, aA2 + 8 * Kp,     b.x, b.y);
                mma_f16(cA, aA2 + 8 * Kp + 4, b.z, b.w);
                mma_f16(cB, aB2 + 8 * Kp,     b.x, b.y);
                mma_f16(cB, aB2 + 8 * Kp + 4, b.z, b.w);
            }
            // layer 4 partials: rows (g: cA0/1, g+8: cA2/3, g+16: cB0/1, g+24: cB2/3)
            #pragma unroll
            for (int e = 0; e < 2; e++) {
                const int j = jc + e;
                float h0 = fmaxf(cA[e],     0.f);
                float h1 = fmaxf(cA[2 + e], 0.f);
                float h2 = fmaxf(cB[e],     0.f);
                float h3 = fmaxf(cB[2 + e], 0.f);
                #pragma unroll
                for (int c = 0; c < 4; c++) {
                    float wv = sW4[c * 128 + j];
                    o[0][c] += h0 * wv;
                    o[1][c] += h1 * wv;
                    o[2][c] += h2 * wv;
                    o[3][c] += h3 * wv;
                }
            }
        }

        // ---- quad reduction + store (4 points per thread at tig==0) ----
        #pragma unroll
        for (int r = 0; r < 4; r++)
            #pragma unroll
            for (int c = 0; c < 4; c++) {
                o[r][c] += __shfl_xor_sync(0xFFFFFFFF, o[r][c], 1);
                o[r][c] += __shfl_xor_sync(0xFFFFFFFF, o[r][c], 2);
            }
        if (tig == 0) {
            #pragma unroll
            for (int r = 0; r < 4; r++) {
                const long long p = base + pw + g + 8 * r;
                float4 res = make_float4(o[r][0] + sB4[0], o[r][1] + sB4[1],
                                         o[r][2] + sB4[2], o[r][3] + sB4[3]);
                *(float4*)(out + p * 4) = res;
            }
        }
        // no per-tile shared state -> no barriers
    }
}

extern "C" void kernel_launch(void* const* d_in, const int* in_sizes, int n_in,
                              void* d_out, int out_size)
{
    const float* x  = (const float*)d_in[0];
    const float* W1 = (const float*)d_in[1];
    const float* b1 = (const float*)d_in[2];
    const float* W2 = (const float*)d_in[3];
    const float* b2 = (const float*)d_in[4];
    const float* W3 = (const float*)d_in[5];
    const float* b3 = (const float*)d_in[6];
    const float* W4 = (const float*)d_in[7];
    const float* b4 = (const float*)d_in[8];
    float* out = (float*)d_out;

    const int n = in_sizes[0] / 6;
    const int ntiles = n / TILE_M;          // 4096
    int grid = 148;
    if (grid > ntiles) grid = ntiles;

    cudaFuncSetAttribute(nerf_mma_kernel,
                         cudaFuncAttributeMaxDynamicSharedMemorySize, SMEM_TOTAL);
    nerf_mma_kernel<<<grid, NTHR, SMEM_TOTAL>>>(
        x, W1, b1, W2, b2, W3, b3, W4, b4, out, ntiles);
}

// round 8
// speedup vs baseline: 12.2954x; 1.2581x over previous
#include <cuda_runtime.h>
#include <cuda_fp16.h>
#include <cstdint>

// Fused NeRF MLP: [N,6] ->128 ->128 ->128 -> [N,4]
// ALL four layers on mma.sync m16n8k16 fp16 (f32 accum).
//  L1: K=6 zero-padded to one k-tile (b1-half = 0)
//  L2/L3: 8 k-tiles from packed smem records (LDS.128 feeds 4 MMAs)
//  L4: N=4 zero-padded to n=8, D-layout stores directly (no shuffles)
// Each warp: 32 points as two m16 rowsets. Activations chain in registers.
// Biases ride in MMA accumulator init; relu fused into fragment packing.

#define NTHR   256      // 8 warps
#define TILE_M 256      // points per CTA tile (32 per warp)

#define PK_BYTES (16*4*32*16)      // 32 KB per hidden layer
#define SM_P2   0
#define SM_P3   (SM_P2 + PK_BYTES)
#define SM_P1   (SM_P3 + PK_BYTES)     // 512 * 4B  = 2048
#define SM_P4   (SM_P1 + 2048)         // 256 * 8B  = 2048
#define SM_B1   (SM_P4 + 2048)         // 512
#define SM_B2   (SM_B1 + 512)
#define SM_B3   (SM_B2 + 512)
#define SM_B4   (SM_B3 + 512)          // 64 (8 floats, cols 4..7 zero)
#define SMEM_TOTAL (SM_B4 + 64)

static __device__ __forceinline__ void mma_f16(float* c, const uint32_t* a,
                                               uint32_t b0, uint32_t b1) {
    asm volatile(
        "mma.sync.aligned.m16n8k16.row.col.f32.f16.f16.f32 "
        "{%0,%1,%2,%3},{%4,%5,%6,%7},{%8,%9},{%0,%1,%2,%3};"
        : "+f"(c[0]), "+f"(c[1]), "+f"(c[2]), "+f"(c[3])
        : "r"(a[0]), "r"(a[1]), "r"(a[2]), "r"(a[3]), "r"(b0), "r"(b1));
}
static __device__ __forceinline__ void mma_f16r(float* c, uint32_t a0,
                                                uint32_t a1, uint32_t a2,
                                                uint32_t a3, uint32_t b0,
                                                uint32_t b1) {
    asm volatile(
        "mma.sync.aligned.m16n8k16.row.col.f32.f16.f16.f32 "
        "{%0,%1,%2,%3},{%4,%5,%6,%7},{%8,%9},{%0,%1,%2,%3};"
        : "+f"(c[0]), "+f"(c[1]), "+f"(c[2]), "+f"(c[3])
        : "r"(a0), "r"(a1), "r"(a2), "r"(a3), "r"(b0), "r"(b1));
}

static __device__ __forceinline__ uint32_t pack_f16(float v0, float v1) {
    uint32_t r;
    asm("cvt.rn.f16x2.f32 %0, %1, %2;" : "=r"(r) : "f"(v1), "f"(v0));
    return r;
}

// relu + pack one finished n-tile (c[4]) into a-frag slots for k-tile K=t>>1
static __device__ __forceinline__ void pack_tile(uint32_t* a, int t,
                                                 const float* c) {
    const int K = t >> 1;
    const int o = (t & 1) ? (4 * K + 2) : (4 * K);
    a[o]     = pack_f16(fmaxf(c[0], 0.f), fmaxf(c[1], 0.f));
    a[o + 1] = pack_f16(fmaxf(c[2], 0.f), fmaxf(c[3], 0.f));
}

__global__ __launch_bounds__(NTHR, 1)
void nerf_mma_kernel(const float* __restrict__ x,
                     const float* __restrict__ W1, const float* __restrict__ b1,
                     const float* __restrict__ W2, const float* __restrict__ b2,
                     const float* __restrict__ W3, const float* __restrict__ b3,
                     const float* __restrict__ W4, const float* __restrict__ b4,
                     float* __restrict__ out, int ntiles)
{
    extern __shared__ char smem[];
    uint4*    sP2 = (uint4*)(smem + SM_P2);
    uint4*    sP3 = (uint4*)(smem + SM_P3);
    uint32_t* sP1 = (uint32_t*)(smem + SM_P1);
    uint2*    sP4 = (uint2*)(smem + SM_P4);
    float* sB1 = (float*)(smem + SM_B1);
    float* sB2 = (float*)(smem + SM_B2);
    float* sB3 = (float*)(smem + SM_B3);
    float* sB4 = (float*)(smem + SM_B4);

    const int tid  = threadIdx.x;
    const int warp = tid >> 5;
    const int lane = tid & 31;
    const int g    = lane >> 2;
    const int tig  = lane & 3;

    // ---- one-time: packed fp16 weight fragment records ----
    for (int idx = tid; idx < 2 * 2048; idx += NTHR) {     // W2 / W3
        const int layer = idx >> 11;
        const int e     = idx & 2047;
        const int t  = e >> 7;
        const int Kp = (e >> 5) & 3;
        const int ln = e & 31;
        const int j  = 8 * t + (ln >> 2);
        const int k0 = 32 * Kp + 2 * (ln & 3);
        const float* W = layer ? W3 : W2;
        uint4 rec;
        rec.x = pack_f16(W[j * 128 + k0],      W[j * 128 + k0 + 1]);
        rec.y = pack_f16(W[j * 128 + k0 + 8],  W[j * 128 + k0 + 9]);
        rec.z = pack_f16(W[j * 128 + k0 + 16], W[j * 128 + k0 + 17]);
        rec.w = pack_f16(W[j * 128 + k0 + 24], W[j * 128 + k0 + 25]);
        (layer ? sP3 : sP2)[e] = rec;
    }
    for (int idx = tid; idx < 512; idx += NTHR) {          // W1 (K=6 pad 16)
        const int t  = idx >> 5;
        const int ln = idx & 31;
        const int j  = 8 * t + (ln >> 2);
        const int k0 = 2 * (ln & 3);
        float v0 = (k0     < 6) ? W1[j * 6 + k0]     : 0.f;
        float v1 = (k0 + 1 < 6) ? W1[j * 6 + k0 + 1] : 0.f;
        sP1[idx] = pack_f16(v0, v1);
    }
    for (int idx = tid; idx < 256; idx += NTHR) {          // W4 (n=4 pad 8)
        const int K  = idx >> 5;
        const int ln = idx & 31;
        const int n  = ln >> 2;
        const int k0 = 16 * K + 2 * (ln & 3);
        uint2 rec;
        if (n < 4) {
            const float* wr = W4 + n * 128 + k0;
            rec.x = pack_f16(wr[0], wr[1]);
            rec.y = pack_f16(wr[8], wr[9]);
        } else rec.x = rec.y = 0u;
        sP4[idx] = rec;
    }
    if (tid < 128) { sB1[tid] = b1[tid]; sB2[tid] = b2[tid]; sB3[tid] = b3[tid]; }
    if (tid < 8)   sB4[tid] = (tid < 4) ? b4[tid] : 0.f;
    __syncthreads();

    const uint4* pk2 = sP2 + lane;
    const uint4* pk3 = sP3 + lane;
    const uint32_t* pk1 = sP1 + lane;
    const uint2* pk4 = sP4 + lane;

    for (int tile = blockIdx.x; tile < ntiles; tile += gridDim.x) {
        const long long base = (long long)tile * TILE_M;
        const int pw = warp * 32;
        // thread's 4 points: rows g, g+8 (rowset A), g+16, g+24 (rowset B)

        uint32_t aA[32], aB[32];     // live fragment buffers
        uint32_t aA2[32], aB2[32];

        // ---- x -> fp16 A-frags (k 0..5, rest zero) ----
        uint32_t xA0 = 0, xA1 = 0, xB0 = 0, xB1 = 0;
        {
            const int k0 = 2 * tig;
            if (tig < 3) {
                const float2 v0 = *(const float2*)(x + (base + pw + g)      * 6 + k0);
                const float2 v1 = *(const float2*)(x + (base + pw + g + 8)  * 6 + k0);
                const float2 v2 = *(const float2*)(x + (base + pw + g + 16) * 6 + k0);
                const float2 v3 = *(const float2*)(x + (base + pw + g + 24) * 6 + k0);
                xA0 = pack_f16(v0.x, v0.y);
                xA1 = pack_f16(v1.x, v1.y);
                xB0 = pack_f16(v2.x, v2.y);
                xB1 = pack_f16(v3.x, v3.y);
            }
        }

        // ---- layer 1: one k-tile MMA per n-tile, bias in accumulator ----
        #pragma unroll
        for (int t = 0; t < 16; t++) {
            const int jc = 8 * t + 2 * tig;
            const uint32_t b0 = pk1[t * 32];
            float cA[4], cB[4];
            cA[0] = cA[2] = cB[0] = cB[2] = sB1[jc];
            cA[1] = cA[3] = cB[1] = cB[3] = sB1[jc + 1];
            mma_f16r(cA, xA0, xA1, 0u, 0u, b0, 0u);
            mma_f16r(cB, xB0, xB1, 0u, 0u, b0, 0u);
            pack_tile(aA, t, cA);
            pack_tile(aB, t, cB);
        }

        // ---- layer 2 ----
        #pragma unroll
        for (int t = 0; t < 16; t++) {
            const int jc = 8 * t + 2 * tig;
            float cA[4], cB[4];
            cA[0] = cA[2] = cB[0] = cB[2] = sB2[jc];
            cA[1] = cA[3] = cB[1] = cB[3] = sB2[jc + 1];
            #pragma unroll
            for (int Kp = 0; Kp < 4; Kp++) {
                uint4 b = pk2[(t * 4 + Kp) * 32];
                mma_f16(cA, aA + 8 * Kp,     b.x, b.y);
                mma_f16(cA, aA + 8 * Kp + 4, b.z, b.w);
                mma_f16(cB, aB + 8 * Kp,     b.x, b.y);
                mma_f16(cB, aB + 8 * Kp + 4, b.z, b.w);
            }
            pack_tile(aA2, t, cA);
            pack_tile(aB2, t, cB);
        }

        // ---- layer 3 (packs back into aA/aB) ----
        #pragma unroll
        for (int t = 0; t < 16; t++) {
            const int jc = 8 * t + 2 * tig;
            float cA[4], cB[4];
            cA[0] = cA[2] = cB[0] = cB[2] = sB3[jc];
            cA[1] = cA[3] = cB[1] = cB[3] = sB3[jc + 1];
            #pragma unroll
            for (int Kp = 0; Kp < 4; Kp++) {
                uint4 b = pk3[(t * 4 + Kp) * 32];
                mma_f16(cA, aA2 + 8 * Kp,     b.x, b.y);
                mma_f16(cA, aA2 + 8 * Kp + 4, b.z, b.w);
                mma_f16(cB, aB2 + 8 * Kp,     b.x, b.y);
                mma_f16(cB, aB2 + 8 * Kp + 4, b.z, b.w);
            }
            pack_tile(aA, t, cA);
            pack_tile(aB, t, cB);
        }

        // ---- layer 4: n=8 (4 valid), accumulate 8 k-tiles ----
        {
            float cA[4], cB[4];
            const float bb0 = (tig < 2) ? sB4[2 * tig]     : 0.f;
            const float bb1 = (tig < 2) ? sB4[2 * tig + 1] : 0.f;
            cA[0] = cA[2] = cB[0] = cB[2] = bb0;
            cA[1] = cA[3] = cB[1] = cB[3] = bb1;
            #pragma unroll
            for (int K = 0; K < 8; K++) {
                uint2 b = pk4[K * 32];
                mma_f16(cA, aA + 4 * K, b.x, b.y);
                mma_f16(cB, aB + 4 * K, b.x, b.y);
            }
            if (tig < 2) {
                float* o0 = out + (base + pw + g)      * 4 + 2 * tig;
                float* o1 = out + (base + pw + g + 8)  * 4 + 2 * tig;
                float* o2 = out + (base + pw + g + 16) * 4 + 2 * tig;
                float* o3 = out + (base + pw + g + 24) * 4 + 2 * tig;
                *(float2*)o0 = make_float2(cA[0], cA[1]);
                *(float2*)o1 = make_float2(cA[2], cA[3]);
                *(float2*)o2 = make_float2(cB[0], cB[1]);
                *(float2*)o3 = make_float2(cB[2], cB[3]);
            }
        }
        // no per-tile shared state -> no barriers
    }
}

extern "C" void kernel_launch(void* const* d_in, const int* in_sizes, int n_in,
                              void* d_out, int out_size)
{
    const float* x  = (const float*)d_in[0];
    const float* W1 = (const float*)d_in[1];
    const float* b1 = (const float*)d_in[2];
    const float* W2 = (const float*)d_in[3];
    const float* b2 = (const float*)d_in[4];
    const float* W3 = (const float*)d_in[5];
    const float* b3 = (const float*)d_in[6];
    const float* W4 = (const float*)d_in[7];
    const float* b4 = (const float*)d_in[8];
    float* out = (float*)d_out;

    const int n = in_sizes[0] / 6;
    const int ntiles = n / TILE_M;          // 4096
    int grid = 148;
    if (grid > ntiles) grid = ntiles;

    cudaFuncSetAttribute(nerf_mma_kernel,
                         cudaFuncAttributeMaxDynamicSharedMemorySize, SMEM_TOTAL);
    nerf_mma_kernel<<<grid, NTHR, SMEM_TOTAL>>>(
        x, W1, b1, W2, b2, W3, b3, W4, b4, out, ntiles);
}